// round 1
// baseline (speedup 1.0000x reference)
#include <cuda_runtime.h>
#include <math.h>

// Problem shape (fixed by reference)
#define B_  2
#define S_  2048
#define E_  1024
#define H_  16
#define D_  64
#define M_  (B_ * S_)     // 4096 rows
#define N3_ (3 * E_)      // 3072 fused qkv cols

// Scratch (static __device__ globals — no runtime allocation)
__device__ float g_q[(size_t)B_ * H_ * S_ * D_];     // 16 MB, head-major [BH, S, D]
__device__ float g_k[(size_t)B_ * H_ * S_ * D_];
__device__ float g_v[(size_t)B_ * H_ * S_ * D_];
__device__ float g_attn[(size_t)M_ * E_];            // 32 MB, [B*S, E]

// ---------------------------------------------------------------------------
// Kernel 1: fused QKV GEMM.  Y = X[4096,1024] @ W[1024,3072] + b,
// scattered into head-major g_q / g_k / g_v.
// 64x64 block tile, BK=16, 256 threads, 4x4 per thread.
// ---------------------------------------------------------------------------
__global__ __launch_bounds__(256) void qkv_gemm_kernel(
    const float* __restrict__ X, const float* __restrict__ W,
    const float* __restrict__ bias)
{
    __shared__ float As[16][64];
    __shared__ float Bs[16][64];

    const int tid  = threadIdx.x;
    const int row0 = blockIdx.y * 64;
    const int col0 = blockIdx.x * 64;
    const int tx   = tid & 15;
    const int ty   = tid >> 4;
    const int arow = tid >> 2;          // 0..63
    const int acol = (tid & 3) << 2;    // 0,4,8,12
    const int brow = tid >> 4;          // 0..15
    const int bcol = (tid & 15) << 2;   // 0..60

    float acc[4][4] = {};

    for (int k0 = 0; k0 < E_; k0 += 16) {
        float4 av = *(const float4*)(X + (size_t)(row0 + arow) * E_ + k0 + acol);
        As[acol + 0][arow] = av.x;
        As[acol + 1][arow] = av.y;
        As[acol + 2][arow] = av.z;
        As[acol + 3][arow] = av.w;
        *(float4*)&Bs[brow][bcol] =
            *(const float4*)(W + (size_t)(k0 + brow) * N3_ + col0 + bcol);
        __syncthreads();
        #pragma unroll
        for (int k = 0; k < 16; ++k) {
            float a[4], b[4];
            #pragma unroll
            for (int i = 0; i < 4; ++i) a[i] = As[k][ty * 4 + i];
            #pragma unroll
            for (int j = 0; j < 4; ++j) b[j] = Bs[k][tx * 4 + j];
            #pragma unroll
            for (int i = 0; i < 4; ++i)
                #pragma unroll
                for (int j = 0; j < 4; ++j)
                    acc[i][j] += a[i] * b[j];
        }
        __syncthreads();
    }

    // Epilogue: add bias, scatter to q/k/v head-major.
    // For a fixed thread, the 4 j-columns stay in one section/head => float4.
    const int cbase = col0 + tx * 4;
    const int sec   = cbase >> 10;          // 0=q,1=k,2=v
    const int e     = cbase & 1023;
    const int h     = e >> 6;
    const int d     = e & 63;
    float* dst = (sec == 0) ? g_q : (sec == 1) ? g_k : g_v;
    float4 bv = *(const float4*)(bias + cbase);

    #pragma unroll
    for (int i = 0; i < 4; ++i) {
        int r    = row0 + ty * 4 + i;
        int bidx = r >> 11;                 // / 2048
        int s    = r & 2047;
        float4 o;
        o.x = acc[i][0] + bv.x;
        o.y = acc[i][1] + bv.y;
        o.z = acc[i][2] + bv.z;
        o.w = acc[i][3] + bv.w;
        *(float4*)(dst + ((size_t)(bidx * H_ + h) * S_ + s) * D_ + d) = o;
    }
}

// ---------------------------------------------------------------------------
// Kernel 2: attention (no causal mask), flash-style online softmax.
// One block = one (b,h) x 64-query tile; loops 64-key tiles over full S.
// K and V share one shared buffer (K dead after S=Q K^T).
// ---------------------------------------------------------------------------
#define QT   64
#define KT   64
#define LDS_ 65   // padded stride (floats)

__global__ __launch_bounds__(256) void attn_kernel()
{
    extern __shared__ float sm[];
    float* Qs = sm;                   // QT x LDS_
    float* KV = sm + QT * LDS_;       // KT x LDS_   (K, then reused for V)
    float* Ss = sm + 2 * QT * LDS_;   // QT x LDS_   (scores -> probs)
    __shared__ float m_s[QT], l_s[QT], al_s[QT];

    const int tid = threadIdx.x;
    const int tx  = tid & 15;
    const int ty  = tid >> 4;
    const int bh  = blockIdx.y;                 // 0..31
    const int q0  = blockIdx.x * QT;
    const float* qp = g_q + (size_t)bh * S_ * D_;
    const float* kp = g_k + (size_t)bh * S_ * D_;
    const float* vp = g_v + (size_t)bh * S_ * D_;
    const float scale = 0.125f;                 // 1/sqrt(64)

    // Load Q tile, pre-scaled
    #pragma unroll
    for (int it = 0; it < 4; ++it) {
        int row = (tid >> 4) + it * 16;
        int c4  = (tid & 15) * 4;
        float4 v = *(const float4*)(qp + (size_t)(q0 + row) * D_ + c4);
        Qs[row * LDS_ + c4 + 0] = v.x * scale;
        Qs[row * LDS_ + c4 + 1] = v.y * scale;
        Qs[row * LDS_ + c4 + 2] = v.z * scale;
        Qs[row * LDS_ + c4 + 3] = v.w * scale;
    }
    if (tid < QT) { m_s[tid] = -3.0e38f; l_s[tid] = 0.0f; }

    float acc[4][4] = {};

    for (int kt = 0; kt < S_ / KT; ++kt) {
        // Load K tile
        #pragma unroll
        for (int it = 0; it < 4; ++it) {
            int row = (tid >> 4) + it * 16;
            int c4  = (tid & 15) * 4;
            float4 v = *(const float4*)(kp + (size_t)(kt * KT + row) * D_ + c4);
            KV[row * LDS_ + c4 + 0] = v.x;
            KV[row * LDS_ + c4 + 1] = v.y;
            KV[row * LDS_ + c4 + 2] = v.z;
            KV[row * LDS_ + c4 + 3] = v.w;
        }
        __syncthreads();

        // S = Q K^T (64x64), 4x4 per thread
        float sv[4][4] = {};
        #pragma unroll 4
        for (int d = 0; d < D_; ++d) {
            float qv[4], kv[4];
            #pragma unroll
            for (int i = 0; i < 4; ++i) qv[i] = Qs[(ty * 4 + i) * LDS_ + d];
            #pragma unroll
            for (int j = 0; j < 4; ++j) kv[j] = KV[(tx * 4 + j) * LDS_ + d];
            #pragma unroll
            for (int i = 0; i < 4; ++i)
                #pragma unroll
                for (int j = 0; j < 4; ++j)
                    sv[i][j] += qv[i] * kv[j];
        }
        #pragma unroll
        for (int i = 0; i < 4; ++i)
            #pragma unroll
            for (int j = 0; j < 4; ++j)
                Ss[(ty * 4 + i) * LDS_ + tx * 4 + j] = sv[i][j];
        __syncthreads();   // S done; K no longer needed

        // Load V tile into KV (all threads), then row softmax (tid<64)
        #pragma unroll
        for (int it = 0; it < 4; ++it) {
            int row = (tid >> 4) + it * 16;
            int c4  = (tid & 15) * 4;
            float4 v = *(const float4*)(vp + (size_t)(kt * KT + row) * D_ + c4);
            KV[row * LDS_ + c4 + 0] = v.x;
            KV[row * LDS_ + c4 + 1] = v.y;
            KV[row * LDS_ + c4 + 2] = v.z;
            KV[row * LDS_ + c4 + 3] = v.w;
        }
        if (tid < QT) {
            const int i = tid;
            float mloc = -3.0e38f;
            #pragma unroll 8
            for (int j = 0; j < KT; ++j) mloc = fmaxf(mloc, Ss[i * LDS_ + j]);
            float mo    = m_s[i];
            float mn    = fmaxf(mo, mloc);
            float alpha = __expf(mo - mn);
            float sum   = 0.0f;
            #pragma unroll 8
            for (int j = 0; j < KT; ++j) {
                float p = __expf(Ss[i * LDS_ + j] - mn);
                Ss[i * LDS_ + j] = p;
                sum += p;
            }
            m_s[i]  = mn;
            l_s[i]  = l_s[i] * alpha + sum;
            al_s[i] = alpha;
        }
        __syncthreads();

        // Rescale accumulators, then O += P V
        #pragma unroll
        for (int i = 0; i < 4; ++i) {
            float a = al_s[ty * 4 + i];
            #pragma unroll
            for (int d = 0; d < 4; ++d) acc[i][d] *= a;
        }
        #pragma unroll 4
        for (int j = 0; j < KT; ++j) {
            float pv[4], vv[4];
            #pragma unroll
            for (int i = 0; i < 4; ++i) pv[i] = Ss[(ty * 4 + i) * LDS_ + j];
            #pragma unroll
            for (int d = 0; d < 4; ++d) vv[d] = KV[j * LDS_ + tx * 4 + d];
            #pragma unroll
            for (int i = 0; i < 4; ++i)
                #pragma unroll
                for (int d = 0; d < 4; ++d)
                    acc[i][d] += pv[i] * vv[d];
        }
        __syncthreads();
    }

    // Write normalized output to g_attn in [B*S, E] layout
    const int b = bh >> 4, h = bh & 15;
    #pragma unroll
    for (int i = 0; i < 4; ++i) {
        int   row = ty * 4 + i;
        float inv = 1.0f / l_s[row];
        float4 o;
        o.x = acc[i][0] * inv;
        o.y = acc[i][1] * inv;
        o.z = acc[i][2] * inv;
        o.w = acc[i][3] * inv;
        *(float4*)(g_attn + ((size_t)b * S_ + q0 + row) * E_ + h * D_ + tx * 4) = o;
    }
}

// ---------------------------------------------------------------------------
// Kernel 3: output projection.  out = g_attn[4096,1024] @ Wp[1024,1024] + bp
// ---------------------------------------------------------------------------
__global__ __launch_bounds__(256) void proj_gemm_kernel(
    const float* __restrict__ Wp, const float* __restrict__ bias,
    float* __restrict__ out)
{
    __shared__ float As[16][64];
    __shared__ float Bs[16][64];

    const int tid  = threadIdx.x;
    const int row0 = blockIdx.y * 64;
    const int col0 = blockIdx.x * 64;
    const int tx   = tid & 15;
    const int ty   = tid >> 4;
    const int arow = tid >> 2;
    const int acol = (tid & 3) << 2;
    const int brow = tid >> 4;
    const int bcol = (tid & 15) << 2;

    float acc[4][4] = {};

    for (int k0 = 0; k0 < E_; k0 += 16) {
        float4 av = *(const float4*)(g_attn + (size_t)(row0 + arow) * E_ + k0 + acol);
        As[acol + 0][arow] = av.x;
        As[acol + 1][arow] = av.y;
        As[acol + 2][arow] = av.z;
        As[acol + 3][arow] = av.w;
        *(float4*)&Bs[brow][bcol] =
            *(const float4*)(Wp + (size_t)(k0 + brow) * E_ + col0 + bcol);
        __syncthreads();
        #pragma unroll
        for (int k = 0; k < 16; ++k) {
            float a[4], b[4];
            #pragma unroll
            for (int i = 0; i < 4; ++i) a[i] = As[k][ty * 4 + i];
            #pragma unroll
            for (int j = 0; j < 4; ++j) b[j] = Bs[k][tx * 4 + j];
            #pragma unroll
            for (int i = 0; i < 4; ++i)
                #pragma unroll
                for (int j = 0; j < 4; ++j)
                    acc[i][j] += a[i] * b[j];
        }
        __syncthreads();
    }

    float4 bv = *(const float4*)(bias + col0 + tx * 4);
    #pragma unroll
    for (int i = 0; i < 4; ++i) {
        int r = row0 + ty * 4 + i;
        float4 o;
        o.x = acc[i][0] + bv.x;
        o.y = acc[i][1] + bv.y;
        o.z = acc[i][2] + bv.z;
        o.w = acc[i][3] + bv.w;
        *(float4*)(out + (size_t)r * E_ + col0 + tx * 4) = o;
    }
}

// ---------------------------------------------------------------------------
extern "C" void kernel_launch(void* const* d_in, const int* in_sizes, int n_in,
                              void* d_out, int out_size)
{
    const float* X  = (const float*)d_in[0];   // hidden_states [2,2048,1024]
    const float* Wa = (const float*)d_in[1];   // c_attn_w [1024,3072]
    const float* ba = (const float*)d_in[2];   // c_attn_b [3072]
    const float* Wp = (const float*)d_in[3];   // c_proj_w [1024,1024]
    const float* bp = (const float*)d_in[4];   // c_proj_b [1024]
    float* out = (float*)d_out;                // [2,2048,1024]

    qkv_gemm_kernel<<<dim3(N3_ / 64, M_ / 64), 256>>>(X, Wa, ba);

    const int attn_smem = 3 * QT * LDS_ * (int)sizeof(float);  // 49920 B
    cudaFuncSetAttribute(attn_kernel,
                         cudaFuncAttributeMaxDynamicSharedMemorySize, attn_smem);
    attn_kernel<<<dim3(S_ / QT, B_ * H_), 256, attn_smem>>>();

    proj_gemm_kernel<<<dim3(E_ / 64, M_ / 64), 256>>>(Wp, bp, out);
}

// round 6
// speedup vs baseline: 1.2222x; 1.2222x over previous
#include <cuda_runtime.h>
#include <cuda_bf16.h>
#include <cstdint>

// Problem shape
#define B_  2
#define S_  2048
#define E_  1024
#define H_  16
#define D_  64
#define M_  (B_ * S_)     // 4096
#define N3_ (3 * E_)      // 3072

// ---------------------------------------------------------------------------
// Scratch (__device__ globals). NEVER passed as kernel args from host:
// host-side symbol decays to the host shadow (readable via ATS on GB300 ->
// silent zeros). All references are inside device code.
// ---------------------------------------------------------------------------
__device__ float g_q[(size_t)M_ * E_];   // head-major [BH, S, D] fp32
__device__ float g_k[(size_t)M_ * E_];
__device__ float g_v[(size_t)M_ * E_];
__device__ float g_attn[(size_t)M_ * E_];

// ---------------------------------------------------------------------------
// Helpers
// ---------------------------------------------------------------------------
// pack two f32 -> bf16x2 (v0 in LOW half)
__device__ __forceinline__ uint32_t pack_bf16x2(float v0, float v1) {
    uint32_t d;
    asm("cvt.rn.bf16x2.f32 %0, %1, %2;" : "=r"(d) : "f"(v1), "f"(v0));
    return d;
}

// split (v0,v1) -> hi bf16x2 and residual bf16x2
__device__ __forceinline__ void split2(float v0, float v1,
                                       uint32_t& h, uint32_t& l) {
    h = pack_bf16x2(v0, v1);
    float h0 = __uint_as_float(h << 16);
    float h1 = __uint_as_float(h & 0xFFFF0000u);
    l = pack_bf16x2(v0 - h0, v1 - h1);
}

__device__ __forceinline__ void mma16816(float* c, const uint32_t* a,
                                         const uint32_t* b) {
    asm volatile(
        "mma.sync.aligned.m16n8k16.row.col.f32.bf16.bf16.f32 "
        "{%0,%1,%2,%3},{%4,%5,%6,%7},{%8,%9},{%0,%1,%2,%3};"
        : "+f"(c[0]), "+f"(c[1]), "+f"(c[2]), "+f"(c[3])
        : "r"(a[0]), "r"(a[1]), "r"(a[2]), "r"(a[3]), "r"(b[0]), "r"(b[1]));
}

// ---------------------------------------------------------------------------
// Tensor-core bf16x3 GEMM:
//   D[m0..+128, n0..+128] = A[M,1024](fp32) @ W[1024,Nld](fp32) + bias
// mode 0: A = param Ain (harness X);   scatter fp32 -> g_q/g_k/g_v head-major
// mode 1: A = g_attn (device-global);  row-major fp32 -> outp
// A tiles coalesced; W transposed on the fly. fp32->bf16 hi/lo at fill time.
// Fragments via plain LDS.32 at documented mma.m16n8k16 coordinates.
// smem row stride 80 B -> conflict-free.
// ---------------------------------------------------------------------------
__global__ __launch_bounds__(256) void gemm_tc(
    const float* __restrict__ Ain, const float* __restrict__ W,
    const float* __restrict__ bias, float* __restrict__ outp,
    int Nld, int mode)
{
    __shared__ __align__(16) char smc[4 * 10240];
    char* sAh = smc;
    char* sAl = smc + 10240;
    char* sBh = smc + 20480;
    char* sBl = smc + 30720;

    const float* A = (mode == 0) ? Ain : g_attn;   // device-side symbol ref

    const int tid = threadIdx.x, lane = tid & 31, wid = tid >> 5;
    const int wm = wid & 1, wn = wid >> 1;
    const int m0 = blockIdx.y * 128, n0 = blockIdx.x * 128;
    const int g = lane >> 2, t = lane & 3;

    float acc[4][4][4] = {};

    for (int kc = 0; kc < 32; ++kc) {
        const int k0 = kc * 32;
        __syncthreads();

        // ---- fill A: 128 rows x 32 k
        #pragma unroll
        for (int i = 0; i < 4; ++i) {
            const int idx = tid + i * 256;
            const int row = idx >> 3;
            const int f4  = idx & 7;
            float4 v = *(const float4*)(A + (size_t)(m0 + row) * 1024 + k0 + f4 * 4);
            uint32_t h01, l01, h23, l23;
            split2(v.x, v.y, h01, l01);
            split2(v.z, v.w, h23, l23);
            *(uint2*)(sAh + row * 80 + f4 * 8) = make_uint2(h01, h23);
            *(uint2*)(sAl + row * 80 + f4 * 8) = make_uint2(l01, l23);
        }

        // ---- fill Bt[n][k] from W[k][n]
        #pragma unroll
        for (int i = 0; i < 4; ++i) {
            const int idx = tid + i * 256;
            const int nn  = idx >> 3;
            const int k4  = (idx & 7) * 4;
            const float* wp = W + (size_t)(k0 + k4) * Nld + n0 + nn;
            float w0 = wp[0];
            float w1 = wp[(size_t)Nld];
            float w2 = wp[(size_t)2 * Nld];
            float w3 = wp[(size_t)3 * Nld];
            uint32_t h01, l01, h23, l23;
            split2(w0, w1, h01, l01);
            split2(w2, w3, h23, l23);
            *(uint2*)(sBh + nn * 80 + k4 * 2) = make_uint2(h01, h23);
            *(uint2*)(sBl + nn * 80 + k4 * 2) = make_uint2(l01, l23);
        }
        __syncthreads();

        // ---- compute: 2 k-steps of 16, warp tile 64x32
        #pragma unroll
        for (int ks = 0; ks < 2; ++ks) {
            const int kb = ks * 32 + t * 4;
            uint32_t afh[4][4], afl[4][4];
            #pragma unroll
            for (int mf = 0; mf < 4; ++mf) {
                const int r0 = (wm * 64 + mf * 16 + g) * 80 + kb;
                const int r1 = r0 + 8 * 80;
                afh[mf][0] = *(const uint32_t*)(sAh + r0);
                afh[mf][1] = *(const uint32_t*)(sAh + r1);
                afh[mf][2] = *(const uint32_t*)(sAh + r0 + 16);
                afh[mf][3] = *(const uint32_t*)(sAh + r1 + 16);
                afl[mf][0] = *(const uint32_t*)(sAl + r0);
                afl[mf][1] = *(const uint32_t*)(sAl + r1);
                afl[mf][2] = *(const uint32_t*)(sAl + r0 + 16);
                afl[mf][3] = *(const uint32_t*)(sAl + r1 + 16);
            }
            uint32_t bfh[4][2], bfl[4][2];
            #pragma unroll
            for (int nf = 0; nf < 4; ++nf) {
                const int nb = (wn * 32 + nf * 8 + g) * 80 + kb;
                bfh[nf][0] = *(const uint32_t*)(sBh + nb);
                bfh[nf][1] = *(const uint32_t*)(sBh + nb + 16);
                bfl[nf][0] = *(const uint32_t*)(sBl + nb);
                bfl[nf][1] = *(const uint32_t*)(sBl + nb + 16);
            }
            #pragma unroll
            for (int mf = 0; mf < 4; ++mf)
                #pragma unroll
                for (int nf = 0; nf < 4; ++nf) {
                    mma16816(acc[mf][nf], afh[mf], bfh[nf]);
                    mma16816(acc[mf][nf], afh[mf], bfl[nf]);
                    mma16816(acc[mf][nf], afl[mf], bfh[nf]);
                }
        }
    }

    // ---- epilogue
    const int qc = t * 2;
    if (mode == 0) {
        const int sec = n0 >> 10;
        float* dst = (sec == 0) ? g_q : (sec == 1) ? g_k : g_v;
        #pragma unroll
        for (int mf = 0; mf < 4; ++mf) {
            #pragma unroll
            for (int nf = 0; nf < 4; ++nf) {
                const int cl = wn * 32 + nf * 8 + qc;
                const int e = (n0 & 1023) + cl;
                const int h = e >> 6, d = e & 63;
                const float b0 = bias[n0 + cl], b1 = bias[n0 + cl + 1];
                #pragma unroll
                for (int half = 0; half < 2; ++half) {
                    const int r = m0 + wm * 64 + mf * 16 + g + half * 8;
                    const int bidx = r >> 11, srow = r & 2047;
                    float2 o = make_float2(acc[mf][nf][half * 2] + b0,
                                           acc[mf][nf][half * 2 + 1] + b1);
                    *(float2*)(dst + ((size_t)(bidx * H_ + h) * S_ + srow) * 64 + d) = o;
                }
            }
        }
    } else {
        #pragma unroll
        for (int mf = 0; mf < 4; ++mf) {
            #pragma unroll
            for (int nf = 0; nf < 4; ++nf) {
                const int c = n0 + wn * 32 + nf * 8 + qc;
                const float b0 = bias[c], b1 = bias[c + 1];
                const int r = m0 + wm * 64 + mf * 16 + g;
                float2 o0 = make_float2(acc[mf][nf][0] + b0, acc[mf][nf][1] + b1);
                float2 o1 = make_float2(acc[mf][nf][2] + b0, acc[mf][nf][3] + b1);
                *(float2*)(outp + (size_t)r * Nld + c) = o0;
                *(float2*)(outp + (size_t)(r + 8) * Nld + c) = o1;
            }
        }
    }
}

// ---------------------------------------------------------------------------
// SIMT flash attention (R1-verified math; 4-lane-parallel softmax)
// ---------------------------------------------------------------------------
#define QT   64
#define KT   64
#define LDS_ 65

__global__ __launch_bounds__(256) void attn_kernel()
{
    extern __shared__ float sm[];
    float* Qs = sm;
    float* KV = sm + QT * LDS_;
    float* Ss = sm + 2 * QT * LDS_;
    __shared__ float m_s[QT], l_s[QT], al_s[QT];

    const int tid = threadIdx.x;
    const int tx  = tid & 15;
    const int ty  = tid >> 4;
    const int bh  = blockIdx.y;
    const int q0  = blockIdx.x * QT;
    const float* qp = g_q + (size_t)bh * S_ * D_;
    const float* kp = g_k + (size_t)bh * S_ * D_;
    const float* vp = g_v + (size_t)bh * S_ * D_;
    const float scale = 0.125f;

    #pragma unroll
    for (int it = 0; it < 4; ++it) {
        int row = (tid >> 4) + it * 16;
        int c4  = (tid & 15) * 4;
        float4 v = *(const float4*)(qp + (size_t)(q0 + row) * D_ + c4);
        Qs[row * LDS_ + c4 + 0] = v.x * scale;
        Qs[row * LDS_ + c4 + 1] = v.y * scale;
        Qs[row * LDS_ + c4 + 2] = v.z * scale;
        Qs[row * LDS_ + c4 + 3] = v.w * scale;
    }
    if (tid < QT) { m_s[tid] = -3.0e38f; l_s[tid] = 0.0f; }

    float acc[4][4] = {};

    for (int kt = 0; kt < S_ / KT; ++kt) {
        #pragma unroll
        for (int it = 0; it < 4; ++it) {
            int row = (tid >> 4) + it * 16;
            int c4  = (tid & 15) * 4;
            float4 v = *(const float4*)(kp + (size_t)(kt * KT + row) * D_ + c4);
            KV[row * LDS_ + c4 + 0] = v.x;
            KV[row * LDS_ + c4 + 1] = v.y;
            KV[row * LDS_ + c4 + 2] = v.z;
            KV[row * LDS_ + c4 + 3] = v.w;
        }
        __syncthreads();

        float sv[4][4] = {};
        #pragma unroll 4
        for (int d = 0; d < D_; ++d) {
            float qv[4], kv[4];
            #pragma unroll
            for (int i = 0; i < 4; ++i) qv[i] = Qs[(ty * 4 + i) * LDS_ + d];
            #pragma unroll
            for (int j = 0; j < 4; ++j) kv[j] = KV[(tx * 4 + j) * LDS_ + d];
            #pragma unroll
            for (int i = 0; i < 4; ++i)
                #pragma unroll
                for (int j = 0; j < 4; ++j)
                    sv[i][j] += qv[i] * kv[j];
        }
        #pragma unroll
        for (int i = 0; i < 4; ++i)
            #pragma unroll
            for (int j = 0; j < 4; ++j)
                Ss[(ty * 4 + i) * LDS_ + tx * 4 + j] = sv[i][j];
        __syncthreads();

        #pragma unroll
        for (int it = 0; it < 4; ++it) {
            int row = (tid >> 4) + it * 16;
            int c4  = (tid & 15) * 4;
            float4 v = *(const float4*)(vp + (size_t)(kt * KT + row) * D_ + c4);
            KV[row * LDS_ + c4 + 0] = v.x;
            KV[row * LDS_ + c4 + 1] = v.y;
            KV[row * LDS_ + c4 + 2] = v.z;
            KV[row * LDS_ + c4 + 3] = v.w;
        }

        // Parallel online softmax: 4 lanes per row, 16 cols each
        {
            const int row  = tid >> 2;
            const int part = tid & 3;
            float* srow = Ss + row * LDS_ + part * 16;
            float mloc = srow[0];
            #pragma unroll
            for (int j = 1; j < 16; ++j) mloc = fmaxf(mloc, srow[j]);
            mloc = fmaxf(mloc, __shfl_xor_sync(0xffffffffu, mloc, 1));
            mloc = fmaxf(mloc, __shfl_xor_sync(0xffffffffu, mloc, 2));
            float mo = m_s[row];
            float mn = fmaxf(mo, mloc);
            float sum = 0.0f;
            #pragma unroll
            for (int j = 0; j < 16; ++j) {
                float p = __expf(srow[j] - mn);
                srow[j] = p;
                sum += p;
            }
            sum += __shfl_xor_sync(0xffffffffu, sum, 1);
            sum += __shfl_xor_sync(0xffffffffu, sum, 2);
            if (part == 0) {
                float alpha = __expf(mo - mn);
                m_s[row]  = mn;
                l_s[row]  = l_s[row] * alpha + sum;
                al_s[row] = alpha;
            }
        }
        __syncthreads();

        #pragma unroll
        for (int i = 0; i < 4; ++i) {
            float a = al_s[ty * 4 + i];
            #pragma unroll
            for (int d = 0; d < 4; ++d) acc[i][d] *= a;
        }
        #pragma unroll 4
        for (int j = 0; j < KT; ++j) {
            float pv[4], vv[4];
            #pragma unroll
            for (int i = 0; i < 4; ++i) pv[i] = Ss[(ty * 4 + i) * LDS_ + j];
            #pragma unroll
            for (int d = 0; d < 4; ++d) vv[d] = KV[j * LDS_ + tx * 4 + d];
            #pragma unroll
            for (int i = 0; i < 4; ++i)
                #pragma unroll
                for (int d = 0; d < 4; ++d)
                    acc[i][d] += pv[i] * vv[d];
        }
        __syncthreads();
    }

    const int b = bh >> 4, h = bh & 15;
    #pragma unroll
    for (int i = 0; i < 4; ++i) {
        int   row = ty * 4 + i;
        float inv = 1.0f / l_s[row];
        float4 o;
        o.x = acc[i][0] * inv;
        o.y = acc[i][1] * inv;
        o.z = acc[i][2] * inv;
        o.w = acc[i][3] * inv;
        *(float4*)(g_attn + ((size_t)b * S_ + q0 + row) * E_ + h * D_ + tx * 4) = o;
    }
}

// ---------------------------------------------------------------------------
extern "C" void kernel_launch(void* const* d_in, const int* in_sizes, int n_in,
                              void* d_out, int out_size)
{
    const float* X  = (const float*)d_in[0];   // [2,2048,1024]
    const float* Wa = (const float*)d_in[1];   // [1024,3072]
    const float* ba = (const float*)d_in[2];   // [3072]
    const float* Wp = (const float*)d_in[3];   // [1024,1024]
    const float* bp = (const float*)d_in[4];   // [1024]
    float* out = (float*)d_out;                // [2,2048,1024]

    const int attn_smem = 3 * QT * LDS_ * (int)sizeof(float);
    cudaFuncSetAttribute(attn_kernel,
                         cudaFuncAttributeMaxDynamicSharedMemorySize, attn_smem);

    // QKV projection on tensor cores (A = X from harness; mode 0)
    gemm_tc<<<dim3(N3_ / 128, M_ / 128), 256>>>(X, Wa, ba, nullptr, N3_, 0);

    // Attention
    attn_kernel<<<dim3(S_ / QT, B_ * H_), 256, attn_smem>>>();

    // Output projection on tensor cores (A = g_attn, selected IN KERNEL; mode 1)
    gemm_tc<<<dim3(E_ / 128, M_ / 128), 256>>>(nullptr, Wp, bp, out, E_, 1);
}

// round 7
// speedup vs baseline: 1.9552x; 1.5997x over previous
#include <cuda_runtime.h>
#include <cuda_bf16.h>
#include <cstdint>

// Problem shape
#define B_  2
#define S_  2048
#define E_  1024
#define H_  16
#define D_  64
#define M_  (B_ * S_)     // 4096
#define N3_ (3 * E_)      // 3072

// ---------------------------------------------------------------------------
// Scratch (__device__ globals). NEVER passed as kernel args from host
// (host-side symbol = host shadow -> silent zeros via ATS on GB300).
// ---------------------------------------------------------------------------
__device__ float g_q[(size_t)M_ * E_];   // head-major [BH, S, D] fp32
__device__ float g_k[(size_t)M_ * E_];
__device__ float g_v[(size_t)M_ * E_];
__device__ float g_attn[(size_t)M_ * E_];

// ---------------------------------------------------------------------------
// Helpers
// ---------------------------------------------------------------------------
__device__ __forceinline__ uint32_t pack_bf16x2(float v0, float v1) {
    uint32_t d;
    asm("cvt.rn.bf16x2.f32 %0, %1, %2;" : "=r"(d) : "f"(v1), "f"(v0));
    return d;
}

__device__ __forceinline__ void split2(float v0, float v1,
                                       uint32_t& h, uint32_t& l) {
    h = pack_bf16x2(v0, v1);
    float h0 = __uint_as_float(h << 16);
    float h1 = __uint_as_float(h & 0xFFFF0000u);
    l = pack_bf16x2(v0 - h0, v1 - h1);
}

__device__ __forceinline__ float ex2f(float x) {
    float y;
    asm("ex2.approx.f32 %0, %1;" : "=f"(y) : "f"(x));
    return y;
}

__device__ __forceinline__ void mma16816(float* c, const uint32_t* a,
                                         const uint32_t* b) {
    asm volatile(
        "mma.sync.aligned.m16n8k16.row.col.f32.bf16.bf16.f32 "
        "{%0,%1,%2,%3},{%4,%5,%6,%7},{%8,%9},{%0,%1,%2,%3};"
        : "+f"(c[0]), "+f"(c[1]), "+f"(c[2]), "+f"(c[3])
        : "r"(a[0]), "r"(a[1]), "r"(a[2]), "r"(a[3]), "r"(b[0]), "r"(b[1]));
}

// ---------------------------------------------------------------------------
// Tensor-core bf16x3 GEMM (VERIFIED in Round 6 — unchanged):
//   D[m0..+128, n0..+128] = A[M,1024](fp32) @ W[1024,Nld](fp32) + bias
// mode 0: A = param Ain (harness X); scatter fp32 -> g_q/g_k/g_v head-major
// mode 1: A = g_attn (device ref);   row-major fp32 -> outp
// ---------------------------------------------------------------------------
__global__ __launch_bounds__(256) void gemm_tc(
    const float* __restrict__ Ain, const float* __restrict__ W,
    const float* __restrict__ bias, float* __restrict__ outp,
    int Nld, int mode)
{
    __shared__ __align__(16) char smc[4 * 10240];
    char* sAh = smc;
    char* sAl = smc + 10240;
    char* sBh = smc + 20480;
    char* sBl = smc + 30720;

    const float* A = (mode == 0) ? Ain : g_attn;

    const int tid = threadIdx.x, lane = tid & 31, wid = tid >> 5;
    const int wm = wid & 1, wn = wid >> 1;
    const int m0 = blockIdx.y * 128, n0 = blockIdx.x * 128;
    const int g = lane >> 2, t = lane & 3;

    float acc[4][4][4] = {};

    for (int kc = 0; kc < 32; ++kc) {
        const int k0 = kc * 32;
        __syncthreads();

        #pragma unroll
        for (int i = 0; i < 4; ++i) {
            const int idx = tid + i * 256;
            const int row = idx >> 3;
            const int f4  = idx & 7;
            float4 v = *(const float4*)(A + (size_t)(m0 + row) * 1024 + k0 + f4 * 4);
            uint32_t h01, l01, h23, l23;
            split2(v.x, v.y, h01, l01);
            split2(v.z, v.w, h23, l23);
            *(uint2*)(sAh + row * 80 + f4 * 8) = make_uint2(h01, h23);
            *(uint2*)(sAl + row * 80 + f4 * 8) = make_uint2(l01, l23);
        }

        #pragma unroll
        for (int i = 0; i < 4; ++i) {
            const int idx = tid + i * 256;
            const int nn  = idx >> 3;
            const int k4  = (idx & 7) * 4;
            const float* wp = W + (size_t)(k0 + k4) * Nld + n0 + nn;
            float w0 = wp[0];
            float w1 = wp[(size_t)Nld];
            float w2 = wp[(size_t)2 * Nld];
            float w3 = wp[(size_t)3 * Nld];
            uint32_t h01, l01, h23, l23;
            split2(w0, w1, h01, l01);
            split2(w2, w3, h23, l23);
            *(uint2*)(sBh + nn * 80 + k4 * 2) = make_uint2(h01, h23);
            *(uint2*)(sBl + nn * 80 + k4 * 2) = make_uint2(l01, l23);
        }
        __syncthreads();

        #pragma unroll
        for (int ks = 0; ks < 2; ++ks) {
            const int kb = ks * 32 + t * 4;
            uint32_t afh[4][4], afl[4][4];
            #pragma unroll
            for (int mf = 0; mf < 4; ++mf) {
                const int r0 = (wm * 64 + mf * 16 + g) * 80 + kb;
                const int r1 = r0 + 8 * 80;
                afh[mf][0] = *(const uint32_t*)(sAh + r0);
                afh[mf][1] = *(const uint32_t*)(sAh + r1);
                afh[mf][2] = *(const uint32_t*)(sAh + r0 + 16);
                afh[mf][3] = *(const uint32_t*)(sAh + r1 + 16);
                afl[mf][0] = *(const uint32_t*)(sAl + r0);
                afl[mf][1] = *(const uint32_t*)(sAl + r1);
                afl[mf][2] = *(const uint32_t*)(sAl + r0 + 16);
                afl[mf][3] = *(const uint32_t*)(sAl + r1 + 16);
            }
            uint32_t bfh[4][2], bfl[4][2];
            #pragma unroll
            for (int nf = 0; nf < 4; ++nf) {
                const int nb = (wn * 32 + nf * 8 + g) * 80 + kb;
                bfh[nf][0] = *(const uint32_t*)(sBh + nb);
                bfh[nf][1] = *(const uint32_t*)(sBh + nb + 16);
                bfl[nf][0] = *(const uint32_t*)(sBl + nb);
                bfl[nf][1] = *(const uint32_t*)(sBl + nb + 16);
            }
            #pragma unroll
            for (int mf = 0; mf < 4; ++mf)
                #pragma unroll
                for (int nf = 0; nf < 4; ++nf) {
                    mma16816(acc[mf][nf], afh[mf], bfh[nf]);
                    mma16816(acc[mf][nf], afh[mf], bfl[nf]);
                    mma16816(acc[mf][nf], afl[mf], bfh[nf]);
                }
        }
    }

    const int qc = t * 2;
    if (mode == 0) {
        const int sec = n0 >> 10;
        float* dst = (sec == 0) ? g_q : (sec == 1) ? g_k : g_v;
        #pragma unroll
        for (int mf = 0; mf < 4; ++mf) {
            #pragma unroll
            for (int nf = 0; nf < 4; ++nf) {
                const int cl = wn * 32 + nf * 8 + qc;
                const int e = (n0 & 1023) + cl;
                const int h = e >> 6, d = e & 63;
                const float b0 = bias[n0 + cl], b1 = bias[n0 + cl + 1];
                #pragma unroll
                for (int half = 0; half < 2; ++half) {
                    const int r = m0 + wm * 64 + mf * 16 + g + half * 8;
                    const int bidx = r >> 11, srow = r & 2047;
                    float2 o = make_float2(acc[mf][nf][half * 2] + b0,
                                           acc[mf][nf][half * 2 + 1] + b1);
                    *(float2*)(dst + ((size_t)(bidx * H_ + h) * S_ + srow) * 64 + d) = o;
                }
            }
        }
    } else {
        #pragma unroll
        for (int mf = 0; mf < 4; ++mf) {
            #pragma unroll
            for (int nf = 0; nf < 4; ++nf) {
                const int c = n0 + wn * 32 + nf * 8 + qc;
                const float b0 = bias[c], b1 = bias[c + 1];
                const int r = m0 + wm * 64 + mf * 16 + g;
                float2 o0 = make_float2(acc[mf][nf][0] + b0, acc[mf][nf][1] + b1);
                float2 o1 = make_float2(acc[mf][nf][2] + b0, acc[mf][nf][3] + b1);
                *(float2*)(outp + (size_t)r * Nld + c) = o0;
                *(float2*)(outp + (size_t)(r + 8) * Nld + c) = o1;
            }
        }
    }
}

// ---------------------------------------------------------------------------
// Tensor-core flash attention (no causal mask), bf16x3 on QK^T and PV.
// Block = (bh, 128 queries). 8 warps x 16 query rows. 64-key tiles.
// Same verified fragment machinery as gemm_tc (plain LDS.32, no ldmatrix).
// smem: Kh/Kl [key][dim], Vth/Vtl [dim][key], stride 144 B (conflict-free).
// ---------------------------------------------------------------------------
#define AST 144
#define ATILE (64 * AST)

__global__ __launch_bounds__(256) void attn_tc()
{
    __shared__ __align__(16) char smc[4 * ATILE];   // 36864 B
    char* sKh = smc;
    char* sKl = smc + ATILE;
    char* sVh = smc + 2 * ATILE;
    char* sVl = smc + 3 * ATILE;

    const int tid = threadIdx.x, lane = tid & 31, wid = tid >> 5;
    const int g = lane >> 2, t = lane & 3;
    const int bh = blockIdx.y, q0 = blockIdx.x * 128;

    const float* qp = g_q + (size_t)bh * S_ * 64;
    const float* kp = g_k + (size_t)bh * S_ * 64;
    const float* vp = g_v + (size_t)bh * S_ * 64;

    // Q fragments, register-resident for the whole kernel.
    // scale = 1/sqrt(64) * log2(e), folded so softmax can use ex2.
    const float qscale = 0.125f * 1.4426950408889634f;
    uint32_t qh[4][4], ql[4][4];
    {
        const int r0 = q0 + wid * 16 + g;
        #pragma unroll
        for (int ks = 0; ks < 4; ++ks) {
            const int c = ks * 16 + t * 2;
            float2 v00 = *(const float2*)(qp + (size_t)r0 * 64 + c);
            float2 v10 = *(const float2*)(qp + (size_t)(r0 + 8) * 64 + c);
            float2 v01 = *(const float2*)(qp + (size_t)r0 * 64 + c + 8);
            float2 v11 = *(const float2*)(qp + (size_t)(r0 + 8) * 64 + c + 8);
            split2(v00.x * qscale, v00.y * qscale, qh[ks][0], ql[ks][0]);
            split2(v10.x * qscale, v10.y * qscale, qh[ks][1], ql[ks][1]);
            split2(v01.x * qscale, v01.y * qscale, qh[ks][2], ql[ks][2]);
            split2(v11.x * qscale, v11.y * qscale, qh[ks][3], ql[ks][3]);
        }
    }

    float oacc[8][4] = {};
    float mst0 = -1e30f, mst1 = -1e30f, lst0 = 0.0f, lst1 = 0.0f;

    for (int kt = 0; kt < 32; ++kt) {
        __syncthreads();
        // ---- fill K [key][dim] hi/lo
        #pragma unroll
        for (int i = 0; i < 4; ++i) {
            const int idx = tid + i * 256;
            const int row = idx >> 4;        // key 0..63
            const int c4  = idx & 15;        // dim group
            float4 v = *(const float4*)(kp + (size_t)(kt * 64 + row) * 64 + c4 * 4);
            uint32_t h01, l01, h23, l23;
            split2(v.x, v.y, h01, l01);
            split2(v.z, v.w, h23, l23);
            *(uint2*)(sKh + row * AST + c4 * 8) = make_uint2(h01, h23);
            *(uint2*)(sKl + row * AST + c4 * 8) = make_uint2(l01, l23);
        }
        // ---- fill V transposed [dim][key] hi/lo
        #pragma unroll
        for (int i = 0; i < 4; ++i) {
            const int idx = tid + i * 256;
            const int row = idx >> 4;        // key
            const int c4  = idx & 15;
            float4 v = *(const float4*)(vp + (size_t)(kt * 64 + row) * 64 + c4 * 4);
            float vv[4] = {v.x, v.y, v.z, v.w};
            #pragma unroll
            for (int j = 0; j < 4; ++j) {
                const int dim = c4 * 4 + j;
                __nv_bfloat16 h = __float2bfloat16(vv[j]);
                __nv_bfloat16 l = __float2bfloat16(vv[j] - __bfloat162float(h));
                *(__nv_bfloat16*)(sVh + dim * AST + row * 2) = h;
                *(__nv_bfloat16*)(sVl + dim * AST + row * 2) = l;
            }
        }
        __syncthreads();

        // ---- S = Q K^T (16 q-rows x 64 keys per warp), bf16x3
        float sacc[8][4] = {};
        #pragma unroll
        for (int nf = 0; nf < 8; ++nf) {
            #pragma unroll
            for (int ks = 0; ks < 4; ++ks) {
                const int nb = (nf * 8 + g) * AST + ks * 32 + t * 4;
                uint32_t b2h[2], b2l[2];
                b2h[0] = *(const uint32_t*)(sKh + nb);
                b2h[1] = *(const uint32_t*)(sKh + nb + 16);
                b2l[0] = *(const uint32_t*)(sKl + nb);
                b2l[1] = *(const uint32_t*)(sKl + nb + 16);
                mma16816(sacc[nf], qh[ks], b2h);
                mma16816(sacc[nf], qh[ks], b2l);
                mma16816(sacc[nf], ql[ks], b2h);
            }
        }

        // ---- online softmax (rows r0 = g, r1 = g+8; 4 lanes/row via shfl)
        float ml0 = -1e30f, ml1 = -1e30f;
        #pragma unroll
        for (int nf = 0; nf < 8; ++nf) {
            ml0 = fmaxf(ml0, fmaxf(sacc[nf][0], sacc[nf][1]));
            ml1 = fmaxf(ml1, fmaxf(sacc[nf][2], sacc[nf][3]));
        }
        ml0 = fmaxf(ml0, __shfl_xor_sync(0xffffffffu, ml0, 1));
        ml0 = fmaxf(ml0, __shfl_xor_sync(0xffffffffu, ml0, 2));
        ml1 = fmaxf(ml1, __shfl_xor_sync(0xffffffffu, ml1, 1));
        ml1 = fmaxf(ml1, __shfl_xor_sync(0xffffffffu, ml1, 2));
        const float mn0 = fmaxf(mst0, ml0), mn1 = fmaxf(mst1, ml1);
        const float a0 = ex2f(mst0 - mn0), a1 = ex2f(mst1 - mn1);
        mst0 = mn0; mst1 = mn1;
        float sum0 = 0.0f, sum1 = 0.0f;
        #pragma unroll
        for (int nf = 0; nf < 8; ++nf) {
            sacc[nf][0] = ex2f(sacc[nf][0] - mn0); sum0 += sacc[nf][0];
            sacc[nf][1] = ex2f(sacc[nf][1] - mn0); sum0 += sacc[nf][1];
            sacc[nf][2] = ex2f(sacc[nf][2] - mn1); sum1 += sacc[nf][2];
            sacc[nf][3] = ex2f(sacc[nf][3] - mn1); sum1 += sacc[nf][3];
        }
        sum0 += __shfl_xor_sync(0xffffffffu, sum0, 1);
        sum0 += __shfl_xor_sync(0xffffffffu, sum0, 2);
        sum1 += __shfl_xor_sync(0xffffffffu, sum1, 1);
        sum1 += __shfl_xor_sync(0xffffffffu, sum1, 2);
        lst0 = lst0 * a0 + sum0;
        lst1 = lst1 * a1 + sum1;
        #pragma unroll
        for (int nf = 0; nf < 8; ++nf) {
            oacc[nf][0] *= a0; oacc[nf][1] *= a0;
            oacc[nf][2] *= a1; oacc[nf][3] *= a1;
        }

        // ---- O += P V.  P built in registers from sacc (A-frag identity:
        // a0 = c{0,1} of n-frag 2kk2, a1 = c{2,3} of 2kk2, a2/a3 from 2kk2+1)
        #pragma unroll
        for (int kk2 = 0; kk2 < 4; ++kk2) {
            uint32_t pah[4], pal[4];
            split2(sacc[2 * kk2][0],     sacc[2 * kk2][1],     pah[0], pal[0]);
            split2(sacc[2 * kk2][2],     sacc[2 * kk2][3],     pah[1], pal[1]);
            split2(sacc[2 * kk2 + 1][0], sacc[2 * kk2 + 1][1], pah[2], pal[2]);
            split2(sacc[2 * kk2 + 1][2], sacc[2 * kk2 + 1][3], pah[3], pal[3]);
            #pragma unroll
            for (int nf = 0; nf < 8; ++nf) {
                const int nb = (nf * 8 + g) * AST + kk2 * 32 + t * 4;
                uint32_t v2h[2], v2l[2];
                v2h[0] = *(const uint32_t*)(sVh + nb);
                v2h[1] = *(const uint32_t*)(sVh + nb + 16);
                v2l[0] = *(const uint32_t*)(sVl + nb);
                v2l[1] = *(const uint32_t*)(sVl + nb + 16);
                mma16816(oacc[nf], pah, v2h);
                mma16816(oacc[nf], pah, v2l);
                mma16816(oacc[nf], pal, v2h);
            }
        }
    }

    // ---- normalize + write fp32 to g_attn [B*S, E]
    const float inv0 = 1.0f / lst0, inv1 = 1.0f / lst1;
    const int b = bh >> 4, h = bh & 15;
    const int r0 = q0 + wid * 16 + g;
    #pragma unroll
    for (int nf = 0; nf < 8; ++nf) {
        const int col = h * 64 + nf * 8 + t * 2;
        *(float2*)(g_attn + (size_t)(b * S_ + r0) * E_ + col) =
            make_float2(oacc[nf][0] * inv0, oacc[nf][1] * inv0);
        *(float2*)(g_attn + (size_t)(b * S_ + r0 + 8) * E_ + col) =
            make_float2(oacc[nf][2] * inv1, oacc[nf][3] * inv1);
    }
}

// ---------------------------------------------------------------------------
extern "C" void kernel_launch(void* const* d_in, const int* in_sizes, int n_in,
                              void* d_out, int out_size)
{
    const float* X  = (const float*)d_in[0];   // [2,2048,1024]
    const float* Wa = (const float*)d_in[1];   // [1024,3072]
    const float* ba = (const float*)d_in[2];   // [3072]
    const float* Wp = (const float*)d_in[3];   // [1024,1024]
    const float* bp = (const float*)d_in[4];   // [1024]
    float* out = (float*)d_out;                // [2,2048,1024]

    // QKV projection (mode 0: scatter to g_q/g_k/g_v)
    gemm_tc<<<dim3(N3_ / 128, M_ / 128), 256>>>(X, Wa, ba, nullptr, N3_, 0);

    // Tensor-core flash attention
    attn_tc<<<dim3(S_ / 128, B_ * H_), 256>>>();

    // Output projection (mode 1: A = g_attn selected in kernel)
    gemm_tc<<<dim3(E_ / 128, M_ / 128), 256>>>(nullptr, Wp, bp, out, E_, 1);
}

// round 8
// speedup vs baseline: 2.3608x; 1.2074x over previous
#include <cuda_runtime.h>
#include <cuda_bf16.h>
#include <cstdint>

// Problem shape
#define B_  2
#define S_  2048
#define E_  1024
#define H_  16
#define D_  64
#define M_  (B_ * S_)     // 4096
#define N3_ (3 * E_)      // 3072

// ---------------------------------------------------------------------------
// Scratch (__device__ globals). NEVER passed as kernel args from host
// (host-side symbol = host shadow -> silent zeros via ATS on GB300).
// ---------------------------------------------------------------------------
__device__ float g_q[(size_t)M_ * E_];   // head-major [BH, S, D] fp32
__device__ float g_k[(size_t)M_ * E_];
__device__ float g_v[(size_t)M_ * E_];
__device__ float g_attn[(size_t)M_ * E_];

// ---------------------------------------------------------------------------
// Helpers
// ---------------------------------------------------------------------------
__device__ __forceinline__ uint32_t pack_bf16x2(float v0, float v1) {
    uint32_t d;
    asm("cvt.rn.bf16x2.f32 %0, %1, %2;" : "=r"(d) : "f"(v1), "f"(v0));
    return d;
}

__device__ __forceinline__ void split2(float v0, float v1,
                                       uint32_t& h, uint32_t& l) {
    h = pack_bf16x2(v0, v1);
    float h0 = __uint_as_float(h << 16);
    float h1 = __uint_as_float(h & 0xFFFF0000u);
    l = pack_bf16x2(v0 - h0, v1 - h1);
}

__device__ __forceinline__ float ex2f(float x) {
    float y;
    asm("ex2.approx.f32 %0, %1;" : "=f"(y) : "f"(x));
    return y;
}

__device__ __forceinline__ void mma16816(float* c, const uint32_t* a,
                                         const uint32_t* b) {
    asm volatile(
        "mma.sync.aligned.m16n8k16.row.col.f32.bf16.bf16.f32 "
        "{%0,%1,%2,%3},{%4,%5,%6,%7},{%8,%9},{%0,%1,%2,%3};"
        : "+f"(c[0]), "+f"(c[1]), "+f"(c[2]), "+f"(c[3])
        : "r"(a[0]), "r"(a[1]), "r"(a[2]), "r"(a[3]), "r"(b[0]), "r"(b[1]));
}

// ---------------------------------------------------------------------------
// Tensor-core bf16x3 GEMM with register prefetch:
//   D[m0..+128, n0..+128] = A[M,1024](fp32) @ W[1024,Nld](fp32) + bias
// mode 0: A = param Ain (harness X); scatter fp32 -> g_q/g_k/g_v head-major
// mode 1: A = g_attn (device ref);   row-major fp32 -> outp
// ---------------------------------------------------------------------------
__global__ __launch_bounds__(256) void gemm_tc(
    const float* __restrict__ Ain, const float* __restrict__ W,
    const float* __restrict__ bias, float* __restrict__ outp,
    int Nld, int mode)
{
    __shared__ __align__(16) char smc[4 * 10240];
    char* sAh = smc;
    char* sAl = smc + 10240;
    char* sBh = smc + 20480;
    char* sBl = smc + 30720;

    const float* A = (mode == 0) ? Ain : g_attn;

    const int tid = threadIdx.x, lane = tid & 31, wid = tid >> 5;
    const int wm = wid & 1, wn = wid >> 1;
    const int m0 = blockIdx.y * 128, n0 = blockIdx.x * 128;
    const int g = lane >> 2, t = lane & 3;

    float acc[4][4][4] = {};

    // Load addressing: thread covers rows {r0+32i}, one 16B chunk per row.
    const int arow0 = tid >> 3;           // 0..31
    const int af4   = tid & 7;            // 0..7
    const int bnn0  = tid >> 3;           // 0..31 (n within tile)
    const int bk4   = (tid & 7) * 4;      // 0..28
    const float* aptr = A + (size_t)(m0 + arow0) * 1024 + af4 * 4;
    const float* bptr = W + (size_t)bk4 * Nld + n0 + bnn0;

    float4 ra[4];
    float  rb[4][4];

    // prologue: load tile 0
    #pragma unroll
    for (int i = 0; i < 4; ++i)
        ra[i] = *(const float4*)(aptr + (size_t)i * 32 * 1024);
    #pragma unroll
    for (int i = 0; i < 4; ++i)
        #pragma unroll
        for (int j = 0; j < 4; ++j)
            rb[i][j] = bptr[(size_t)j * Nld + i * 32];

    for (int kc = 0; kc < 32; ++kc) {
        // ---- store regs (tile kc) to smem with hi/lo split
        #pragma unroll
        for (int i = 0; i < 4; ++i) {
            const int row = arow0 + i * 32;
            uint32_t h01, l01, h23, l23;
            split2(ra[i].x, ra[i].y, h01, l01);
            split2(ra[i].z, ra[i].w, h23, l23);
            *(uint2*)(sAh + row * 80 + af4 * 8) = make_uint2(h01, h23);
            *(uint2*)(sAl + row * 80 + af4 * 8) = make_uint2(l01, l23);
        }
        #pragma unroll
        for (int i = 0; i < 4; ++i) {
            const int nn = bnn0 + i * 32;
            uint32_t h01, l01, h23, l23;
            split2(rb[i][0], rb[i][1], h01, l01);
            split2(rb[i][2], rb[i][3], h23, l23);
            *(uint2*)(sBh + nn * 80 + bk4 * 2) = make_uint2(h01, h23);
            *(uint2*)(sBl + nn * 80 + bk4 * 2) = make_uint2(l01, l23);
        }
        __syncthreads();

        // ---- prefetch tile kc+1 (overlaps with compute below)
        if (kc + 1 < 32) {
            const int k0n = (kc + 1) * 32;
            #pragma unroll
            for (int i = 0; i < 4; ++i)
                ra[i] = *(const float4*)(aptr + (size_t)i * 32 * 1024 + k0n);
            #pragma unroll
            for (int i = 0; i < 4; ++i)
                #pragma unroll
                for (int j = 0; j < 4; ++j)
                    rb[i][j] = bptr[(size_t)(k0n + j) * Nld + i * 32];
        }

        // ---- compute: 2 k-steps of 16, warp tile 64x32
        #pragma unroll
        for (int ks = 0; ks < 2; ++ks) {
            const int kb = ks * 32 + t * 4;
            uint32_t afh[4][4], afl[4][4];
            #pragma unroll
            for (int mf = 0; mf < 4; ++mf) {
                const int r0 = (wm * 64 + mf * 16 + g) * 80 + kb;
                const int r1 = r0 + 8 * 80;
                afh[mf][0] = *(const uint32_t*)(sAh + r0);
                afh[mf][1] = *(const uint32_t*)(sAh + r1);
                afh[mf][2] = *(const uint32_t*)(sAh + r0 + 16);
                afh[mf][3] = *(const uint32_t*)(sAh + r1 + 16);
                afl[mf][0] = *(const uint32_t*)(sAl + r0);
                afl[mf][1] = *(const uint32_t*)(sAl + r1);
                afl[mf][2] = *(const uint32_t*)(sAl + r0 + 16);
                afl[mf][3] = *(const uint32_t*)(sAl + r1 + 16);
            }
            uint32_t bfh[4][2], bfl[4][2];
            #pragma unroll
            for (int nf = 0; nf < 4; ++nf) {
                const int nb = (wn * 32 + nf * 8 + g) * 80 + kb;
                bfh[nf][0] = *(const uint32_t*)(sBh + nb);
                bfh[nf][1] = *(const uint32_t*)(sBh + nb + 16);
                bfl[nf][0] = *(const uint32_t*)(sBl + nb);
                bfl[nf][1] = *(const uint32_t*)(sBl + nb + 16);
            }
            #pragma unroll
            for (int mf = 0; mf < 4; ++mf)
                #pragma unroll
                for (int nf = 0; nf < 4; ++nf) {
                    mma16816(acc[mf][nf], afh[mf], bfh[nf]);
                    mma16816(acc[mf][nf], afh[mf], bfl[nf]);
                    mma16816(acc[mf][nf], afl[mf], bfh[nf]);
                }
        }
        __syncthreads();
    }

    const int qc = t * 2;
    if (mode == 0) {
        const int sec = n0 >> 10;
        float* dst = (sec == 0) ? g_q : (sec == 1) ? g_k : g_v;
        #pragma unroll
        for (int mf = 0; mf < 4; ++mf) {
            #pragma unroll
            for (int nf = 0; nf < 4; ++nf) {
                const int cl = wn * 32 + nf * 8 + qc;
                const int e = (n0 & 1023) + cl;
                const int h = e >> 6, d = e & 63;
                const float b0 = bias[n0 + cl], b1 = bias[n0 + cl + 1];
                #pragma unroll
                for (int half = 0; half < 2; ++half) {
                    const int r = m0 + wm * 64 + mf * 16 + g + half * 8;
                    const int bidx = r >> 11, srow = r & 2047;
                    float2 o = make_float2(acc[mf][nf][half * 2] + b0,
                                           acc[mf][nf][half * 2 + 1] + b1);
                    *(float2*)(dst + ((size_t)(bidx * H_ + h) * S_ + srow) * 64 + d) = o;
                }
            }
        }
    } else {
        #pragma unroll
        for (int mf = 0; mf < 4; ++mf) {
            #pragma unroll
            for (int nf = 0; nf < 4; ++nf) {
                const int c = n0 + wn * 32 + nf * 8 + qc;
                const float b0 = bias[c], b1 = bias[c + 1];
                const int r = m0 + wm * 64 + mf * 16 + g;
                float2 o0 = make_float2(acc[mf][nf][0] + b0, acc[mf][nf][1] + b1);
                float2 o1 = make_float2(acc[mf][nf][2] + b0, acc[mf][nf][3] + b1);
                *(float2*)(outp + (size_t)r * Nld + c) = o0;
                *(float2*)(outp + (size_t)(r + 8) * Nld + c) = o1;
            }
        }
    }
}

// ---------------------------------------------------------------------------
// Tensor-core flash attention (no causal mask), bf16x3 on QK^T and PV.
// Block = (bh, 128 queries). 8 warps x 16 query rows. 64-key tiles.
// V fill now via 4x4 register-block transpose (LDG.128 + STS.64).
// ---------------------------------------------------------------------------
#define AST 144
#define ATILE (64 * AST)

__global__ __launch_bounds__(256) void attn_tc()
{
    __shared__ __align__(16) char smc[4 * ATILE];   // 36864 B
    char* sKh = smc;
    char* sKl = smc + ATILE;
    char* sVh = smc + 2 * ATILE;
    char* sVl = smc + 3 * ATILE;

    const int tid = threadIdx.x, lane = tid & 31, wid = tid >> 5;
    const int g = lane >> 2, t = lane & 3;
    const int bh = blockIdx.y, q0 = blockIdx.x * 128;

    const float* qp = g_q + (size_t)bh * S_ * 64;
    const float* kp = g_k + (size_t)bh * S_ * 64;
    const float* vp = g_v + (size_t)bh * S_ * 64;

    // Q fragments, register-resident. scale = 1/sqrt(64) * log2(e).
    const float qscale = 0.125f * 1.4426950408889634f;
    uint32_t qh[4][4], ql[4][4];
    {
        const int r0 = q0 + wid * 16 + g;
        #pragma unroll
        for (int ks = 0; ks < 4; ++ks) {
            const int c = ks * 16 + t * 2;
            float2 v00 = *(const float2*)(qp + (size_t)r0 * 64 + c);
            float2 v10 = *(const float2*)(qp + (size_t)(r0 + 8) * 64 + c);
            float2 v01 = *(const float2*)(qp + (size_t)r0 * 64 + c + 8);
            float2 v11 = *(const float2*)(qp + (size_t)(r0 + 8) * 64 + c + 8);
            split2(v00.x * qscale, v00.y * qscale, qh[ks][0], ql[ks][0]);
            split2(v10.x * qscale, v10.y * qscale, qh[ks][1], ql[ks][1]);
            split2(v01.x * qscale, v01.y * qscale, qh[ks][2], ql[ks][2]);
            split2(v11.x * qscale, v11.y * qscale, qh[ks][3], ql[ks][3]);
        }
    }

    // V-transpose fill coordinates (4 keys x 4 dims per thread)
    const int vk4 = (tid & 15) * 4;   // key base
    const int vd4 = (tid >> 4) * 4;   // dim base

    float oacc[8][4] = {};
    float mst0 = -1e30f, mst1 = -1e30f, lst0 = 0.0f, lst1 = 0.0f;

    for (int kt = 0; kt < 32; ++kt) {
        __syncthreads();
        // ---- fill K [key][dim] hi/lo (coalesced)
        #pragma unroll
        for (int i = 0; i < 4; ++i) {
            const int idx = tid + i * 256;
            const int row = idx >> 4;
            const int c4  = idx & 15;
            float4 v = *(const float4*)(kp + (size_t)(kt * 64 + row) * 64 + c4 * 4);
            uint32_t h01, l01, h23, l23;
            split2(v.x, v.y, h01, l01);
            split2(v.z, v.w, h23, l23);
            *(uint2*)(sKh + row * AST + c4 * 8) = make_uint2(h01, h23);
            *(uint2*)(sKl + row * AST + c4 * 8) = make_uint2(l01, l23);
        }
        // ---- fill V transposed [dim][key]: 4x4 register-block transpose
        {
            float4 rv[4];
            #pragma unroll
            for (int kk = 0; kk < 4; ++kk)
                rv[kk] = *(const float4*)(vp + (size_t)(kt * 64 + vk4 + kk) * 64 + vd4);
            const float* fv = (const float*)rv;   // fv[kk*4 + dd]
            #pragma unroll
            for (int dd = 0; dd < 4; ++dd) {
                uint32_t h01, l01, h23, l23;
                split2(fv[0 * 4 + dd], fv[1 * 4 + dd], h01, l01);
                split2(fv[2 * 4 + dd], fv[3 * 4 + dd], h23, l23);
                *(uint2*)(sVh + (vd4 + dd) * AST + vk4 * 2) = make_uint2(h01, h23);
                *(uint2*)(sVl + (vd4 + dd) * AST + vk4 * 2) = make_uint2(l01, l23);
            }
        }
        __syncthreads();

        // ---- S = Q K^T (16 q-rows x 64 keys per warp), bf16x3
        float sacc[8][4] = {};
        #pragma unroll
        for (int nf = 0; nf < 8; ++nf) {
            #pragma unroll
            for (int ks = 0; ks < 4; ++ks) {
                const int nb = (nf * 8 + g) * AST + ks * 32 + t * 4;
                uint32_t b2h[2], b2l[2];
                b2h[0] = *(const uint32_t*)(sKh + nb);
                b2h[1] = *(const uint32_t*)(sKh + nb + 16);
                b2l[0] = *(const uint32_t*)(sKl + nb);
                b2l[1] = *(const uint32_t*)(sKl + nb + 16);
                mma16816(sacc[nf], qh[ks], b2h);
                mma16816(sacc[nf], qh[ks], b2l);
                mma16816(sacc[nf], ql[ks], b2h);
            }
        }

        // ---- online softmax
        float ml0 = -1e30f, ml1 = -1e30f;
        #pragma unroll
        for (int nf = 0; nf < 8; ++nf) {
            ml0 = fmaxf(ml0, fmaxf(sacc[nf][0], sacc[nf][1]));
            ml1 = fmaxf(ml1, fmaxf(sacc[nf][2], sacc[nf][3]));
        }
        ml0 = fmaxf(ml0, __shfl_xor_sync(0xffffffffu, ml0, 1));
        ml0 = fmaxf(ml0, __shfl_xor_sync(0xffffffffu, ml0, 2));
        ml1 = fmaxf(ml1, __shfl_xor_sync(0xffffffffu, ml1, 1));
        ml1 = fmaxf(ml1, __shfl_xor_sync(0xffffffffu, ml1, 2));
        const float mn0 = fmaxf(mst0, ml0), mn1 = fmaxf(mst1, ml1);
        const float a0 = ex2f(mst0 - mn0), a1 = ex2f(mst1 - mn1);
        mst0 = mn0; mst1 = mn1;
        float sum0 = 0.0f, sum1 = 0.0f;
        #pragma unroll
        for (int nf = 0; nf < 8; ++nf) {
            sacc[nf][0] = ex2f(sacc[nf][0] - mn0); sum0 += sacc[nf][0];
            sacc[nf][1] = ex2f(sacc[nf][1] - mn0); sum0 += sacc[nf][1];
            sacc[nf][2] = ex2f(sacc[nf][2] - mn1); sum1 += sacc[nf][2];
            sacc[nf][3] = ex2f(sacc[nf][3] - mn1); sum1 += sacc[nf][3];
        }
        sum0 += __shfl_xor_sync(0xffffffffu, sum0, 1);
        sum0 += __shfl_xor_sync(0xffffffffu, sum0, 2);
        sum1 += __shfl_xor_sync(0xffffffffu, sum1, 1);
        sum1 += __shfl_xor_sync(0xffffffffu, sum1, 2);
        lst0 = lst0 * a0 + sum0;
        lst1 = lst1 * a1 + sum1;
        #pragma unroll
        for (int nf = 0; nf < 8; ++nf) {
            oacc[nf][0] *= a0; oacc[nf][1] *= a0;
            oacc[nf][2] *= a1; oacc[nf][3] *= a1;
        }

        // ---- O += P V
        #pragma unroll
        for (int kk2 = 0; kk2 < 4; ++kk2) {
            uint32_t pah[4], pal[4];
            split2(sacc[2 * kk2][0],     sacc[2 * kk2][1],     pah[0], pal[0]);
            split2(sacc[2 * kk2][2],     sacc[2 * kk2][3],     pah[1], pal[1]);
            split2(sacc[2 * kk2 + 1][0], sacc[2 * kk2 + 1][1], pah[2], pal[2]);
            split2(sacc[2 * kk2 + 1][2], sacc[2 * kk2 + 1][3], pah[3], pal[3]);
            #pragma unroll
            for (int nf = 0; nf < 8; ++nf) {
                const int nb = (nf * 8 + g) * AST + kk2 * 32 + t * 4;
                uint32_t v2h[2], v2l[2];
                v2h[0] = *(const uint32_t*)(sVh + nb);
                v2h[1] = *(const uint32_t*)(sVh + nb + 16);
                v2l[0] = *(const uint32_t*)(sVl + nb);
                v2l[1] = *(const uint32_t*)(sVl + nb + 16);
                mma16816(oacc[nf], pah, v2h);
                mma16816(oacc[nf], pah, v2l);
                mma16816(oacc[nf], pal, v2h);
            }
        }
    }

    // ---- normalize + write fp32 to g_attn [B*S, E]
    const float inv0 = 1.0f / lst0, inv1 = 1.0f / lst1;
    const int b = bh >> 4, h = bh & 15;
    const int r0 = q0 + wid * 16 + g;
    #pragma unroll
    for (int nf = 0; nf < 8; ++nf) {
        const int col = h * 64 + nf * 8 + t * 2;
        *(float2*)(g_attn + (size_t)(b * S_ + r0) * E_ + col) =
            make_float2(oacc[nf][0] * inv0, oacc[nf][1] * inv0);
        *(float2*)(g_attn + (size_t)(b * S_ + r0 + 8) * E_ + col) =
            make_float2(oacc[nf][2] * inv1, oacc[nf][3] * inv1);
    }
}

// ---------------------------------------------------------------------------
extern "C" void kernel_launch(void* const* d_in, const int* in_sizes, int n_in,
                              void* d_out, int out_size)
{
    const float* X  = (const float*)d_in[0];   // [2,2048,1024]
    const float* Wa = (const float*)d_in[1];   // [1024,3072]
    const float* ba = (const float*)d_in[2];   // [3072]
    const float* Wp = (const float*)d_in[3];   // [1024,1024]
    const float* bp = (const float*)d_in[4];   // [1024]
    float* out = (float*)d_out;                // [2,2048,1024]

    // QKV projection (mode 0: scatter to g_q/g_k/g_v)
    gemm_tc<<<dim3(N3_ / 128, M_ / 128), 256>>>(X, Wa, ba, nullptr, N3_, 0);

    // Tensor-core flash attention
    attn_tc<<<dim3(S_ / 128, B_ * H_), 256>>>();

    // Output projection (mode 1: A = g_attn selected in kernel)
    gemm_tc<<<dim3(E_ / 128, M_ / 128), 256>>>(nullptr, Wp, bp, out, E_, 1);
}